// round 13
// baseline (speedup 1.0000x reference)
#include <cuda_runtime.h>
#include <cuda_bf16.h>
#include <math.h>
#include <stdint.h>

#define BB 32
#define SC 128
#define NM 16
#define DM 512
#define HH 8
#define DH 64
#define NC 39998
#define MQ (BB*NM)    /* 512 gathered query rows */
#define KP2 256       /* packed pairs per row (DM/2) */
#define NCHUNK 313    /* ceil(NC/128) */
#define WP ((long)DM*KP2)   /* pairs per 512x512 matrix = 131072 */

// ---------------- scratch (device globals; no allocation allowed) -------------
__device__ float g_KV[BB*SC*1024];     // K cols 0..511, V cols 512..1023
__device__ float g_Q[MQ*DM];
__device__ float g_attn[MQ*DM];
__device__ float g_bKV[1024];
__device__ float2 g_part[NCHUNK*MQ];   // per (chunk,row) partial (max, sumexp)

// packed bf16 hi/lo operands
__device__ unsigned g_pk_currH[BB*SC*KP2];
__device__ unsigned g_pk_currL[BB*SC*KP2];
__device__ unsigned g_pk_wkvH[1024*KP2];
__device__ unsigned g_pk_wkvL[1024*KP2];
__device__ unsigned g_pk_wqH[DM*KP2];
__device__ unsigned g_pk_wqL[DM*KP2];
__device__ unsigned g_pk_t2H[DM*KP2];
__device__ unsigned g_pk_t2L[DM*KP2];
__device__ unsigned g_pk_hybH[MQ*KP2];
__device__ unsigned g_pk_hybL[MQ*KP2];

// ---------------- bf16 split helper ------------------------------------------
__device__ __forceinline__ void split_pack(float x, float y,
                                           unsigned& hi, unsigned& lo) {
    __nv_bfloat16 hx = __float2bfloat16_rn(x);
    __nv_bfloat16 hy = __float2bfloat16_rn(y);
    float rx = x - __bfloat162float(hx);
    float ry = y - __bfloat162float(hy);
    __nv_bfloat16 lx = __float2bfloat16_rn(rx);
    __nv_bfloat16 ly = __float2bfloat16_rn(ry);
    hi = ((unsigned)__bfloat16_as_ushort(hy) << 16) | __bfloat16_as_ushort(hx);
    lo = ((unsigned)__bfloat16_as_ushort(ly) << 16) | __bfloat16_as_ushort(lx);
}

// ---------------- merged prologue: all independent elementwise prep -----------
// ranges: [0,2WP) wk|wv ; [2WP,4WP) wq,t2 ; [4WP,4WP+1024) bias ; then gather_pe
__global__ void prologue_kernel(const int* __restrict__ mask_curr,
                                const float* __restrict__ emb,
                                const float* __restrict__ wk, const float* __restrict__ wv,
                                const float* __restrict__ wq, const float* __restrict__ t2w,
                                const float* __restrict__ bk, const float* __restrict__ bv,
                                unsigned* __restrict__ wkvH, unsigned* __restrict__ wkvL,
                                unsigned* __restrict__ wqH,  unsigned* __restrict__ wqL,
                                unsigned* __restrict__ t2H,  unsigned* __restrict__ t2L,
                                float* __restrict__ bKV,
                                unsigned* __restrict__ cH,   unsigned* __restrict__ cL) {
    long i = (long)blockIdx.x * blockDim.x + threadIdx.x;
    const long R1 = 2 * WP;            // end of wkv region
    const long R2 = 4 * WP;            // end of wq/t2 region
    const long R3 = R2 + 1024;         // end of bias region
    const long R4 = R3 + (long)BB * SC * KP2;

    if (i < R1) {
        const float* src = (i < WP) ? wk : wv;
        long j = (i < WP) ? i : i - WP;
        float2 v = ((const float2*)src)[j];
        split_pack(v.x, v.y, wkvH[i], wkvL[i]);
    } else if (i < R2) {
        long j = i - R1;
        if (j < WP) {
            float2 v = ((const float2*)wq)[j];
            split_pack(v.x, v.y, wqH[j], wqL[j]);
        } else {
            long k = j - WP;
            float2 v = ((const float2*)t2w)[k];
            split_pack(v.x, v.y, t2H[k], t2L[k]);
        }
    } else if (i < R3) {
        int t = (int)(i - R2);
        bKV[t] = (t < 512) ? bk[t] : bv[t - 512];
    } else if (i < R4) {
        long j = i - R3;                 // pair index into curr
        int pp  = (int)(j & (KP2 - 1));
        int row = (int)(j / KP2);
        int s   = row & (SC - 1);
        int g   = mask_curr[row];
        int d0  = pp * 2;
        float freq = expf((float)d0 * -0.0179889460176f);  // -ln(10000)/512
        float ang  = (float)s * freq;
        float v0 = emb[(size_t)g * DM + d0]     + sinf(ang);
        float v1 = emb[(size_t)g * DM + d0 + 1] + cosf(ang);
        split_pack(v0, v1, cH[j], cL[j]);
    }
}

// ---------------- mma / ldmatrix / cp.async helpers ----------------------------
__device__ __forceinline__ void mma_bf16(float* c, const unsigned* a, const unsigned* b) {
    asm("mma.sync.aligned.m16n8k16.row.col.f32.bf16.bf16.f32 "
        "{%0,%1,%2,%3}, {%4,%5,%6,%7}, {%8,%9}, {%0,%1,%2,%3};"
        : "+f"(c[0]), "+f"(c[1]), "+f"(c[2]), "+f"(c[3])
        : "r"(a[0]), "r"(a[1]), "r"(a[2]), "r"(a[3]), "r"(b[0]), "r"(b[1]));
}
__device__ __forceinline__ void cp16(void* dst, const void* src, bool ok) {
    unsigned d = (unsigned)__cvta_generic_to_shared(dst);
    int sz = ok ? 16 : 0;
    asm volatile("cp.async.cg.shared.global [%0], [%1], 16, %2;"
                 :: "r"(d), "l"(src), "r"(sz));
}
#define LDSM4(r, a)                                                          \
    asm volatile("ldmatrix.sync.aligned.m8n8.x4.shared.b16 {%0,%1,%2,%3}, [%4];" \
                 : "=r"((r)[0]), "=r"((r)[1]), "=r"((r)[2]), "=r"((r)[3])    \
                 : "r"(a))

#define PITCH 20
#define TSZ (128*PITCH)
#define F32SZ (128*32)   /* f32 staging tile, uint32 units (16 KB) */

// ======== fragment-load + mma block shared by all GEMM variants ==============
#define MMA_STEP(baseAH, baseAL, baseBH, baseBL)                                 \
    _Pragma("unroll")                                                            \
    for (int ks = 0; ks < 2; ++ks) {                                             \
        int kc = ks * 8;                                                         \
        unsigned ah[4][4], al[4][4];                                             \
        _Pragma("unroll")                                                        \
        for (int mt = 0; mt < 4; ++mt) {                                         \
            uint32_t off = (uint32_t)(((a_row + mt * 16) * PITCH + kc + a_col) * 4); \
            LDSM4(ah[mt], (baseAH) + off);                                       \
            LDSM4(al[mt], (baseAL) + off);                                       \
        }                                                                        \
        unsigned bh[4][2], bl[4][2];                                             \
        _Pragma("unroll")                                                        \
        for (int np = 0; np < 2; ++np) {                                         \
            uint32_t off = (uint32_t)(((b_row + np * 16) * PITCH + kc + b_col) * 4); \
            unsigned rh[4], rl[4];                                               \
            LDSM4(rh, (baseBH) + off);                                           \
            LDSM4(rl, (baseBL) + off);                                           \
            bh[np * 2][0]     = rh[0]; bh[np * 2][1]     = rh[1];                \
            bh[np * 2 + 1][0] = rh[2]; bh[np * 2 + 1][1] = rh[3];                \
            bl[np * 2][0]     = rl[0]; bl[np * 2][1]     = rl[1];                \
            bl[np * 2 + 1][0] = rl[2]; bl[np * 2 + 1][1] = rl[3];                \
        }                                                                        \
        _Pragma("unroll")                                                        \
        for (int mt = 0; mt < 4; ++mt)                                           \
            _Pragma("unroll")                                                    \
            for (int nt = 0; nt < 4; ++nt)                                       \
                mma_bf16(acc[mt][nt], ah[mt], bh[nt]);                           \
        _Pragma("unroll")                                                        \
        for (int mt = 0; mt < 4; ++mt)                                           \
            _Pragma("unroll")                                                    \
            for (int nt = 0; nt < 4; ++nt)                                       \
                mma_bf16(acc[mt][nt], al[mt], bh[nt]);                           \
        _Pragma("unroll")                                                        \
        for (int mt = 0; mt < 4; ++mt)                                           \
            _Pragma("unroll")                                                    \
            for (int nt = 0; nt < 4; ++nt)                                       \
                mma_bf16(acc[mt][nt], ah[mt], bl[nt]);                           \
    }

#define GEMM_PROLOG()                                                            \
    int bm = blockIdx.x * 128;                                                   \
    int bn = blockIdx.y * 128;                                                   \
    int tid = threadIdx.x;                                                       \
    int wid = tid >> 5;                                                          \
    int lane = tid & 31;                                                         \
    int warp_m = wid >> 2;                                                       \
    int warp_n = wid & 3;                                                        \
    int g  = lane >> 2;                                                          \
    int tg = lane & 3;                                                           \
    int m_base = warp_m * 64;                                                    \
    int n_base = warp_n * 32;                                                    \
    int a_row = m_base + (lane & 15);                                            \
    int a_col = (lane >> 4) * 4;                                                 \
    int b_row = n_base + ((lane >> 4) & 1) * 8 + (lane & 7);                     \
    int b_col = ((lane >> 3) & 1) * 4;                                           \
    float acc[4][4][4];                                                          \
    _Pragma("unroll")                                                            \
    for (int mt = 0; mt < 4; ++mt)                                               \
        _Pragma("unroll")                                                        \
        for (int nt = 0; nt < 4; ++nt)                                           \
            _Pragma("unroll")                                                    \
            for (int i = 0; i < 4; ++i) acc[mt][nt][i] = 0.f;                    \
    int srow0 = tid >> 2;                                                        \
    int sc4   = (tid & 3) * 4;                                                   \
    int srow1 = (tid + 256) >> 2;

#define STAGE_PK(buf, k0p)                                                       \
    {                                                                            \
        unsigned* bAH = sm + (buf) * 4 * TSZ;                                    \
        unsigned* bAL = bAH + TSZ;                                               \
        unsigned* bBH = bAH + 2 * TSZ;                                           \
        unsigned* bBL = bAH + 3 * TSZ;                                           \
        _Pragma("unroll")                                                        \
        for (int i = 0; i < 2; ++i) {                                            \
            int row = i ? srow1 : srow0;                                         \
            cp16(bAH + row * PITCH + sc4, AH + (size_t)(bm + row) * KP2 + (k0p) + sc4, true); \
            cp16(bAL + row * PITCH + sc4, AL + (size_t)(bm + row) * KP2 + (k0p) + sc4, true); \
            int nrow = bn + row;                                                 \
            bool ok = nrow < N;                                                  \
            size_t bro = (size_t)(ok ? nrow : 0) * KP2 + (k0p) + sc4;            \
            cp16(bBH + row * PITCH + sc4, BH + bro, ok);                         \
            cp16(bBL + row * PITCH + sc4, BL + bro, ok);                         \
        }                                                                        \
        asm volatile("cp.async.commit_group;");                                  \
    }

#define GEMM_MAINLOOP()                                                          \
    STAGE_PK(0, 0);                                                              \
    const int NSTEP = DM / 32;                                                   \
    for (int s = 0; s < NSTEP; ++s) {                                            \
        if (s + 1 < NSTEP) {                                                     \
            STAGE_PK((s + 1) & 1, (s + 1) * 16);                                 \
            asm volatile("cp.async.wait_group 1;");                              \
        } else {                                                                 \
            asm volatile("cp.async.wait_group 0;");                              \
        }                                                                        \
        __syncthreads();                                                         \
        uint32_t baseAH = smem_u32 + ((s & 1) * 4 * TSZ) * 4;                    \
        MMA_STEP(baseAH, baseAH + TSZ * 4, baseAH + 2 * TSZ * 4, baseAH + 3 * TSZ * 4); \
        __syncthreads();                                                         \
    }

// ---------------- GEMM variant 1: packed A/B, f32 C + bias --------------------
__global__ __launch_bounds__(256, 2)
void gemm_pk_kernel(const unsigned* __restrict__ AH, const unsigned* __restrict__ AL,
                    const unsigned* __restrict__ BH, const unsigned* __restrict__ BL,
                    const float* __restrict__ bias,
                    float* __restrict__ C,
                    int M, int N, int ldc) {
    extern __shared__ unsigned sm[];
    uint32_t smem_u32 = (uint32_t)__cvta_generic_to_shared(sm);
    GEMM_PROLOG();
    GEMM_MAINLOOP();

#pragma unroll
    for (int mt = 0; mt < 4; ++mt) {
        int row0 = bm + m_base + mt * 16 + g;
#pragma unroll
        for (int nt = 0; nt < 4; ++nt) {
            int col0 = bn + n_base + nt * 8 + 2 * tg;
            float b0 = bias ? bias[col0] : 0.f;
            float b1 = bias ? bias[col0 + 1] : 0.f;
            C[(size_t)row0 * ldc + col0]           = acc[mt][nt][0] + b0;
            C[(size_t)row0 * ldc + col0 + 1]       = acc[mt][nt][1] + b1;
            C[(size_t)(row0 + 8) * ldc + col0]     = acc[mt][nt][2] + b0;
            C[(size_t)(row0 + 8) * ldc + col0 + 1] = acc[mt][nt][3] + b1;
        }
    }
}

// ---------------- GEMM variant 1b: Q projection with fused mask gather --------
__global__ __launch_bounds__(256, 2)
void gemm_pk_qproj_kernel(const int* __restrict__ mask_pos,
                          const unsigned* __restrict__ AH, const unsigned* __restrict__ AL,
                          const unsigned* __restrict__ BH, const unsigned* __restrict__ BL,
                          const float* __restrict__ bias,
                          float* __restrict__ C) {
    extern __shared__ unsigned sm[];
    uint32_t smem_u32 = (uint32_t)__cvta_generic_to_shared(sm);
    const int ldc = DM;
    GEMM_PROLOG();

    int gr0 = bm + srow0;
    int gr1 = bm + srow1;
    size_t abase0 = (((size_t)(gr0 >> 4)) * SC + mask_pos[gr0]) * KP2 + sc4;
    size_t abase1 = (((size_t)(gr1 >> 4)) * SC + mask_pos[gr1]) * KP2 + sc4;

#define STAGE_QP(buf, k0p)                                                       \
    {                                                                            \
        unsigned* bAH = sm + (buf) * 4 * TSZ;                                    \
        unsigned* bAL = bAH + TSZ;                                               \
        unsigned* bBH = bAH + 2 * TSZ;                                           \
        unsigned* bBL = bAH + 3 * TSZ;                                           \
        cp16(bAH + srow0 * PITCH + sc4, AH + abase0 + (k0p), true);              \
        cp16(bAL + srow0 * PITCH + sc4, AL + abase0 + (k0p), true);              \
        cp16(bAH + srow1 * PITCH + sc4, AH + abase1 + (k0p), true);              \
        cp16(bAL + srow1 * PITCH + sc4, AL + abase1 + (k0p), true);              \
        cp16(bBH + srow0 * PITCH + sc4, BH + (size_t)(bn + srow0) * KP2 + (k0p) + sc4, true); \
        cp16(bBL + srow0 * PITCH + sc4, BL + (size_t)(bn + srow0) * KP2 + (k0p) + sc4, true); \
        cp16(bBH + srow1 * PITCH + sc4, BH + (size_t)(bn + srow1) * KP2 + (k0p) + sc4, true); \
        cp16(bBL + srow1 * PITCH + sc4, BL + (size_t)(bn + srow1) * KP2 + (k0p) + sc4, true); \
        asm volatile("cp.async.commit_group;");                                  \
    }

    STAGE_QP(0, 0);
    const int NSTEP = DM / 32;
    for (int s = 0; s < NSTEP; ++s) {
        if (s + 1 < NSTEP) {
            STAGE_QP((s + 1) & 1, (s + 1) * 16);
            asm volatile("cp.async.wait_group 1;");
        } else {
            asm volatile("cp.async.wait_group 0;");
        }
        __syncthreads();
        uint32_t baseAH = smem_u32 + ((s & 1) * 4 * TSZ) * 4;
        MMA_STEP(baseAH, baseAH + TSZ * 4, baseAH + 2 * TSZ * 4, baseAH + 3 * TSZ * 4);
        __syncthreads();
    }
#undef STAGE_QP

#pragma unroll
    for (int mt = 0; mt < 4; ++mt) {
        int row0 = bm + m_base + mt * 16 + g;
#pragma unroll
        for (int nt = 0; nt < 4; ++nt) {
            int col0 = bn + n_base + nt * 8 + 2 * tg;
            float b0 = bias[col0], b1 = bias[col0 + 1];
            C[(size_t)row0 * ldc + col0]           = acc[mt][nt][0] + b0;
            C[(size_t)row0 * ldc + col0 + 1]       = acc[mt][nt][1] + b1;
            C[(size_t)(row0 + 8) * ldc + col0]     = acc[mt][nt][2] + b0;
            C[(size_t)(row0 + 8) * ldc + col0 + 1] = acc[mt][nt][3] + b1;
        }
    }
}

// ---------------- GEMM variant 2: t2 with fused tanh(A) conversion + packout ---
// A = attn f32; staged as f32, converted (tanhf + split_pack) in-kernel.
// Bit-identical to old prepack(tanh)+packed GEMM path.
__global__ __launch_bounds__(256, 2)
void gemm_t2_kernel(const float* __restrict__ Af,
                    const unsigned* __restrict__ BH, const unsigned* __restrict__ BL,
                    const float* __restrict__ bias,
                    unsigned* __restrict__ CH, unsigned* __restrict__ CL) {
    extern __shared__ unsigned sm[];
    uint32_t smem_u32 = (uint32_t)__cvta_generic_to_shared(sm);
    GEMM_PROLOG();
    int frow = tid >> 3;        // 0..31 f32 staging row group
    int fq   = (tid & 7) * 4;   // float col within 32

#define STAGE_T2(buf, s)                                                         \
    {                                                                            \
        unsigned* bAH = sm + (buf) * 4 * TSZ;                                    \
        unsigned* bBH = bAH + 2 * TSZ;                                           \
        unsigned* bBL = bAH + 3 * TSZ;                                           \
        float* aF = (float*)(sm + 8 * TSZ + (buf) * F32SZ);                      \
        int k0p = (s) * 16;                                                      \
        _Pragma("unroll")                                                        \
        for (int j = 0; j < 4; ++j) {                                            \
            int row = frow + j * 32;                                             \
            cp16(aF + row * 32 + fq, Af + (size_t)(bm + row) * DM + (s) * 32 + fq, true); \
        }                                                                        \
        cp16(bBH + srow0 * PITCH + sc4, BH + (size_t)(bn + srow0) * KP2 + k0p + sc4, true); \
        cp16(bBL + srow0 * PITCH + sc4, BL + (size_t)(bn + srow0) * KP2 + k0p + sc4, true); \
        cp16(bBH + srow1 * PITCH + sc4, BH + (size_t)(bn + srow1) * KP2 + k0p + sc4, true); \
        cp16(bBL + srow1 * PITCH + sc4, BL + (size_t)(bn + srow1) * KP2 + k0p + sc4, true); \
        asm volatile("cp.async.commit_group;");                                  \
    }

    STAGE_T2(0, 0);
    const int NSTEP = DM / 32;
    for (int s = 0; s < NSTEP; ++s) {
        if (s + 1 < NSTEP) {
            STAGE_T2((s + 1) & 1, s + 1);
            asm volatile("cp.async.wait_group 1;");
        } else {
            asm volatile("cp.async.wait_group 0;");
        }
        __syncthreads();

        // convert f32 A -> tanh -> packed hi/lo
        {
            unsigned* bAH = sm + (s & 1) * 4 * TSZ;
            unsigned* bAL = bAH + TSZ;
            const float* aF = (const float*)(sm + 8 * TSZ + (s & 1) * F32SZ);
#pragma unroll
            for (int j = 0; j < 8; ++j) {
                int idx = tid + j * 256;
                int row = idx >> 4;
                int p   = idx & 15;
                float x = tanhf(aF[row * 32 + 2 * p]);
                float y = tanhf(aF[row * 32 + 2 * p + 1]);
                split_pack(x, y, bAH[row * PITCH + p], bAL[row * PITCH + p]);
            }
        }
        __syncthreads();

        uint32_t baseAH = smem_u32 + ((s & 1) * 4 * TSZ) * 4;
        MMA_STEP(baseAH, baseAH + TSZ * 4, baseAH + 2 * TSZ * 4, baseAH + 3 * TSZ * 4);
        __syncthreads();
    }
#undef STAGE_T2

#pragma unroll
    for (int mt = 0; mt < 4; ++mt) {
        int row0 = bm + m_base + mt * 16 + g;
#pragma unroll
        for (int nt = 0; nt < 4; ++nt) {
            int col0 = bn + n_base + nt * 8 + 2 * tg;
            float b0 = bias[col0], b1 = bias[col0 + 1];
            float v0 = acc[mt][nt][0] + b0, v1 = acc[mt][nt][1] + b1;
            float v2 = acc[mt][nt][2] + b0, v3 = acc[mt][nt][3] + b1;
            size_t p0 = (size_t)row0 * KP2 + (col0 >> 1);
            size_t p1 = (size_t)(row0 + 8) * KP2 + (col0 >> 1);
            split_pack(v0, v1, CH[p0], CL[p0]);
            split_pack(v2, v3, CH[p1], CL[p1]);
        }
    }
}

// ---------------- GEMM variant 3: scores, f32 B (emb) converted in-kernel ------
__global__ __launch_bounds__(256, 2)
void gemm_score_kernel(const unsigned* __restrict__ AH, const unsigned* __restrict__ AL,
                       const float* __restrict__ Bf,   // emb + 2*DM
                       float* __restrict__ C,
                       float2* __restrict__ part,
                       int N) {
    extern __shared__ unsigned sm[];
    uint32_t smem_u32 = (uint32_t)__cvta_generic_to_shared(sm);
    GEMM_PROLOG();
    int brow = tid >> 3;
    int bq   = (tid & 7) * 4;

#define STAGE_SC(buf, s)                                                         \
    {                                                                            \
        unsigned* bAH = sm + (buf) * 4 * TSZ;                                    \
        unsigned* bAL = bAH + TSZ;                                               \
        float* bF = (float*)(sm + 8 * TSZ + (buf) * F32SZ);                      \
        int k0p = (s) * 16;                                                      \
        cp16(bAH + srow0 * PITCH + sc4, AH + (size_t)(bm + srow0) * KP2 + k0p + sc4, true); \
        cp16(bAL + srow0 * PITCH + sc4, AL + (size_t)(bm + srow0) * KP2 + k0p + sc4, true); \
        cp16(bAH + srow1 * PITCH + sc4, AH + (size_t)(bm + srow1) * KP2 + k0p + sc4, true); \
        cp16(bAL + srow1 * PITCH + sc4, AL + (size_t)(bm + srow1) * KP2 + k0p + sc4, true); \
        _Pragma("unroll")                                                        \
        for (int j = 0; j < 4; ++j) {                                            \
            int row = brow + j * 32;                                             \
            int nrow = bn + row;                                                 \
            bool ok = nrow < N;                                                  \
            cp16(bF + row * 32 + bq,                                             \
                 Bf + (size_t)(ok ? nrow : 0) * DM + (s) * 32 + bq, ok);         \
        }                                                                        \
        asm volatile("cp.async.commit_group;");                                  \
    }

    STAGE_SC(0, 0);
    const int NSTEP = DM / 32;
    for (int s = 0; s < NSTEP; ++s) {
        if (s + 1 < NSTEP) {
            STAGE_SC((s + 1) & 1, s + 1);
            asm volatile("cp.async.wait_group 1;");
        } else {
            asm volatile("cp.async.wait_group 0;");
        }
        __syncthreads();

        // convert f32 B -> packed hi/lo (bit-identical to split_pack)
        {
            unsigned* bAH0 = sm + (s & 1) * 4 * TSZ;
            unsigned* bBH = bAH0 + 2 * TSZ;
            unsigned* bBL = bAH0 + 3 * TSZ;
            const float* bF = (const float*)(sm + 8 * TSZ + (s & 1) * F32SZ);
#pragma unroll
            for (int j = 0; j < 8; ++j) {
                int idx = tid + j * 256;
                int row = idx >> 4;
                int p   = idx & 15;
                float x = bF[row * 32 + 2 * p];
                float y = bF[row * 32 + 2 * p + 1];
                unsigned hi;
                asm("cvt.rn.bf16x2.f32 %0, %1, %2;" : "=r"(hi) : "f"(y), "f"(x));
                float hx = __uint_as_float(hi << 16);
                float hy = __uint_as_float(hi & 0xFFFF0000u);
                unsigned lo;
                asm("cvt.rn.bf16x2.f32 %0, %1, %2;" : "=r"(lo) : "f"(y - hy), "f"(x - hx));
                bBH[row * PITCH + p] = hi;
                bBL[row * PITCH + p] = lo;
            }
        }
        __syncthreads();

        uint32_t baseAH = smem_u32 + ((s & 1) * 4 * TSZ) * 4;
        MMA_STEP(baseAH, baseAH + TSZ * 4, baseAH + 2 * TSZ * 4, baseAH + 3 * TSZ * 4);
        __syncthreads();
    }
#undef STAGE_SC

    // epilogue: store C + per-row (max, sumexp) partials
    float2* red = (float2*)sm;
#pragma unroll
    for (int mt = 0; mt < 4; ++mt) {
        int rl0 = m_base + mt * 16 + g;
        int row0 = bm + rl0;
        float m0 = -INFINITY, s0 = 0.f, m1 = -INFINITY, s1 = 0.f;
#pragma unroll
        for (int nt = 0; nt < 4; ++nt) {
            int col0 = bn + n_base + nt * 8 + 2 * tg;
            float v00 = acc[mt][nt][0], v01 = acc[mt][nt][1];
            float v10 = acc[mt][nt][2], v11 = acc[mt][nt][3];
            if (col0 < N) {
                C[(size_t)row0 * N + col0]       = v00;
                C[(size_t)(row0 + 8) * N + col0] = v10;
                float nm0 = fmaxf(m0, v00); s0 = s0 * __expf(m0 - nm0) + __expf(v00 - nm0); m0 = nm0;
                float nm1 = fmaxf(m1, v10); s1 = s1 * __expf(m1 - nm1) + __expf(v10 - nm1); m1 = nm1;
            }
            if (col0 + 1 < N) {
                C[(size_t)row0 * N + col0 + 1]       = v01;
                C[(size_t)(row0 + 8) * N + col0 + 1] = v11;
                float nm0 = fmaxf(m0, v01); s0 = s0 * __expf(m0 - nm0) + __expf(v01 - nm0); m0 = nm0;
                float nm1 = fmaxf(m1, v11); s1 = s1 * __expf(m1 - nm1) + __expf(v11 - nm1); m1 = nm1;
            }
        }
        int slot = warp_n * 4 + tg;
        red[rl0 * 16 + slot]       = make_float2(m0, s0);
        red[(rl0 + 8) * 16 + slot] = make_float2(m1, s1);
    }
    __syncthreads();
    if (tid < 128) {
        float m = -INFINITY, s = 0.f;
#pragma unroll
        for (int k = 0; k < 16; ++k) {
            float2 v = red[tid * 16 + k];
            float nm = fmaxf(m, v.x);
            s = s * __expf(m - nm) + v.y * __expf(v.x - nm);
            m = nm;
        }
        part[(size_t)blockIdx.y * MQ + bm + tid] = make_float2(m, s);
    }
}

// ---------------- attention (reads merged KV, ld=1024) ------------------------
__global__ __launch_bounds__(256)
void attn_kernel(const float* __restrict__ Q,
                 const float* __restrict__ KV,
                 float* __restrict__ out) {
    int blk = blockIdx.x;
    int b = blk / HH, h = blk % HH;

    __shared__ float sQ[NM][DH];
    __shared__ float sS[NM][SC];
    __shared__ float sKV[SC][DH + 1];

    int tid = threadIdx.x;

    for (int e = tid; e < NM * DH; e += 256) {
        int m = e / DH, d0 = e % DH;
        sQ[m][d0] = Q[((size_t)b * NM + m) * DM + h * DH + d0];
    }
    for (int e = tid; e < SC * DH; e += 256) {
        int k = e / DH, d0 = e % DH;
        sKV[k][d0] = KV[((size_t)b * SC + k) * 1024 + h * DH + d0];
    }
    __syncthreads();

    for (int e = tid; e < NM * SC; e += 256) {
        int m = e / SC, k = e % SC;
        float acc = 0.f;
#pragma unroll
        for (int d0 = 0; d0 < DH; ++d0) acc += sQ[m][d0] * sKV[k][d0];
        sS[m][k] = acc;
    }
    __syncthreads();

    int w = tid >> 5, lane = tid & 31;
    for (int m = 2 * w; m < 2 * w + 2; ++m) {
        float vals[4];
        float mx = -INFINITY;
#pragma unroll
        for (int j = 0; j < 4; ++j) {
            vals[j] = sS[m][lane * 4 + j];
            mx = fmaxf(mx, vals[j]);
        }
#pragma unroll
        for (int off = 16; off; off >>= 1)
            mx = fmaxf(mx, __shfl_xor_sync(0xffffffffu, mx, off));
        float sum = 0.f;
#pragma unroll
        for (int j = 0; j < 4; ++j) {
            vals[j] = expf(vals[j] - mx);
            sum += vals[j];
        }
#pragma unroll
        for (int off = 16; off; off >>= 1)
            sum += __shfl_xor_sync(0xffffffffu, sum, off);
        float inv = 1.f / sum;
#pragma unroll
        for (int j = 0; j < 4; ++j) sS[m][lane * 4 + j] = vals[j] * inv;
    }
    __syncthreads();

    for (int e = tid; e < SC * DH; e += 256) {
        int k = e / DH, d0 = e % DH;
        sKV[k][d0] = KV[((size_t)b * SC + k) * 1024 + 512 + h * DH + d0];
    }
    __syncthreads();

    for (int e = tid; e < NM * DH; e += 256) {
        int m = e / DH, d0 = e % DH;
        float acc = 0.f;
#pragma unroll
        for (int k = 0; k < SC; ++k) acc += sS[m][k] * sKV[k][d0];
        out[((size_t)b * NM + m) * DM + h * DH + d0] = acc;
    }
}

// ---------------- fused LSE reduce + subtract (block per row) -----------------
__global__ __launch_bounds__(256)
void lse_sub_kernel(const float2* __restrict__ part, float* __restrict__ out) {
    int row = blockIdx.x;
    __shared__ float rm[256], rs[256];
    int t = threadIdx.x;

    float m = -INFINITY, s = 0.f;
    for (int c = t; c < NCHUNK; c += 256) {
        float2 v = part[(size_t)c * MQ + row];
        float nm = fmaxf(m, v.x);
        s = s * __expf(m - nm) + v.y * __expf(v.x - nm);
        m = nm;
    }
    rm[t] = m; rs[t] = s;
    __syncthreads();
    for (int st = 128; st; st >>= 1) {
        if (t < st) {
            float m2 = rm[t + st], s2 = rs[t + st];
            float nm = fmaxf(rm[t], m2);
            rs[t] = rs[t] * __expf(rm[t] - nm) + s2 * __expf(m2 - nm);
            rm[t] = nm;
        }
        __syncthreads();
    }
    float lse = rm[0] + logf(rs[0]);

    float* p = out + (size_t)row * NC;
    for (int i = t; i < NC; i += 256) p[i] -= lse;
}

// ---------------- launch -----------------------------------------------------
extern "C" void kernel_launch(void* const* d_in, const int* in_sizes, int n_in,
                              void* d_out, int out_size) {
    const int*   mask_pos  = (const int*)d_in[2];
    const int*   mask_curr = (const int*)d_in[3];
    const float* emb       = (const float*)d_in[5];
    const float* c_wq = (const float*)d_in[12];
    const float* c_bq = (const float*)d_in[13];
    const float* c_wk = (const float*)d_in[14];
    const float* c_bk = (const float*)d_in[15];
    const float* c_wv = (const float*)d_in[16];
    const float* c_bv = (const float*)d_in[17];
    const float* t2_w = (const float*)d_in[24];
    const float* t2_b = (const float*)d_in[25];
    float* out = (float*)d_out;

    float *KV, *Qb, *attn, *bKV;
    float2* part;
    cudaGetSymbolAddress((void**)&KV,   g_KV);
    cudaGetSymbolAddress((void**)&Qb,   g_Q);
    cudaGetSymbolAddress((void**)&attn, g_attn);
    cudaGetSymbolAddress((void**)&bKV,  g_bKV);
    cudaGetSymbolAddress((void**)&part, g_part);

    unsigned *currH, *currL, *wkvH, *wkvL, *wqH, *wqL, *t2H, *t2L, *hybH, *hybL;
    cudaGetSymbolAddress((void**)&currH, g_pk_currH);
    cudaGetSymbolAddress((void**)&currL, g_pk_currL);
    cudaGetSymbolAddress((void**)&wkvH,  g_pk_wkvH);
    cudaGetSymbolAddress((void**)&wkvL,  g_pk_wkvL);
    cudaGetSymbolAddress((void**)&wqH,   g_pk_wqH);
    cudaGetSymbolAddress((void**)&wqL,   g_pk_wqL);
    cudaGetSymbolAddress((void**)&t2H,   g_pk_t2H);
    cudaGetSymbolAddress((void**)&t2L,   g_pk_t2L);
    cudaGetSymbolAddress((void**)&hybH,  g_pk_hybH);
    cudaGetSymbolAddress((void**)&hybL,  g_pk_hybL);

    const int SMEMB  = 2 * 4 * TSZ * 4;                // 81920 B
    const int SMEMSC = (8 * TSZ + 2 * F32SZ) * 4;      // 114688 B
    cudaFuncSetAttribute(gemm_pk_kernel,
                         cudaFuncAttributeMaxDynamicSharedMemorySize, SMEMB);
    cudaFuncSetAttribute(gemm_pk_qproj_kernel,
                         cudaFuncAttributeMaxDynamicSharedMemorySize, SMEMB);
    cudaFuncSetAttribute(gemm_t2_kernel,
                         cudaFuncAttributeMaxDynamicSharedMemorySize, SMEMSC);
    cudaFuncSetAttribute(gemm_score_kernel,
                         cudaFuncAttributeMaxDynamicSharedMemorySize, SMEMSC);

    // 0: merged prologue (all weight prepacks + bias + gather_pe)
    {
        long total = 4 * WP + 1024 + (long)BB * SC * KP2;
        prologue_kernel<<<(int)((total + 255) / 256), 256>>>(
            mask_curr, emb, c_wk, c_wv, c_wq, t2_w, c_bk, c_bv,
            wkvH, wkvL, wqH, wqL, t2H, t2L, bKV, currH, currL);
    }
    // 1: Q projection with fused mask gather
    {
        dim3 g(MQ / 128, DM / 128);
        gemm_pk_qproj_kernel<<<g, 256, SMEMB>>>(mask_pos, currH, currL, wqH, wqL, c_bq, Qb);
    }
    // 2: merged K|V projection [4096, 1024]
    {
        dim3 g((BB * SC) / 128, 1024 / 128);
        gemm_pk_kernel<<<g, 256, SMEMB>>>(currH, currL, wkvH, wkvL, bKV, KV,
                                          BB * SC, 1024, 1024);
    }
    // 3: attention
    attn_kernel<<<BB * HH, 256>>>(Qb, KV, attn);
    // 4: t2 GEMM with fused tanh(A) conversion, packed output
    {
        dim3 g(MQ / 128, DM / 128);
        gemm_t2_kernel<<<g, 256, SMEMSC>>>(attn, t2H, t2L, t2_b, hybH, hybL);
    }
    // 5: scores GEMM (ncu -s 5 lands here)
    {
        dim3 g(MQ / 128, NCHUNK);
        gemm_score_kernel<<<g, 256, SMEMSC>>>(hybH, hybL, emb + 2 * DM, out, part, NC);
    }
    // 6: fused lse reduce + subtract
    lse_sub_kernel<<<MQ, 256>>>(part, out);
}

// round 14
// speedup vs baseline: 1.0104x; 1.0104x over previous
#include <cuda_runtime.h>
#include <cuda_bf16.h>
#include <math.h>
#include <stdint.h>

#define BB 32
#define SC 128
#define NM 16
#define DM 512
#define HH 8
#define DH 64
#define NC 39998
#define MQ (BB*NM)    /* 512 gathered query rows */
#define KP2 256       /* packed pairs per row (DM/2) */
#define NCHUNK 313    /* ceil(NC/128) */
#define WP ((long)DM*KP2)   /* pairs per 512x512 matrix = 131072 */

// ---------------- scratch (device globals; no allocation allowed) -------------
__device__ float g_KV[BB*SC*1024];     // K cols 0..511, V cols 512..1023
__device__ float g_Q[MQ*DM];
__device__ float g_attn[MQ*DM];
__device__ float g_bKV[1024];
__device__ float2 g_part[NCHUNK*MQ];   // per (chunk,row) partial (max, sumexp)

// packed bf16 hi/lo operands
__device__ unsigned g_pk_currH[BB*SC*KP2];
__device__ unsigned g_pk_currL[BB*SC*KP2];
__device__ unsigned g_pk_wkvH[1024*KP2];
__device__ unsigned g_pk_wkvL[1024*KP2];
__device__ unsigned g_pk_wqH[DM*KP2];
__device__ unsigned g_pk_wqL[DM*KP2];
__device__ unsigned g_pk_t2H[DM*KP2];
__device__ unsigned g_pk_t2L[DM*KP2];
__device__ unsigned g_pk_hybH[MQ*KP2];
__device__ unsigned g_pk_hybL[MQ*KP2];

// ---------------- bf16 split helper ------------------------------------------
__device__ __forceinline__ void split_pack(float x, float y,
                                           unsigned& hi, unsigned& lo) {
    __nv_bfloat16 hx = __float2bfloat16_rn(x);
    __nv_bfloat16 hy = __float2bfloat16_rn(y);
    float rx = x - __bfloat162float(hx);
    float ry = y - __bfloat162float(hy);
    __nv_bfloat16 lx = __float2bfloat16_rn(rx);
    __nv_bfloat16 ly = __float2bfloat16_rn(ry);
    hi = ((unsigned)__bfloat16_as_ushort(hy) << 16) | __bfloat16_as_ushort(hx);
    lo = ((unsigned)__bfloat16_as_ushort(ly) << 16) | __bfloat16_as_ushort(lx);
}

// ---------------- merged prologue: all independent elementwise prep -----------
__global__ void prologue_kernel(const int* __restrict__ mask_curr,
                                const float* __restrict__ emb,
                                const float* __restrict__ wk, const float* __restrict__ wv,
                                const float* __restrict__ wq, const float* __restrict__ t2w,
                                const float* __restrict__ bk, const float* __restrict__ bv,
                                unsigned* __restrict__ wkvH, unsigned* __restrict__ wkvL,
                                unsigned* __restrict__ wqH,  unsigned* __restrict__ wqL,
                                unsigned* __restrict__ t2H,  unsigned* __restrict__ t2L,
                                float* __restrict__ bKV,
                                unsigned* __restrict__ cH,   unsigned* __restrict__ cL) {
    long i = (long)blockIdx.x * blockDim.x + threadIdx.x;
    const long R1 = 2 * WP;
    const long R2 = 4 * WP;
    const long R3 = R2 + 1024;
    const long R4 = R3 + (long)BB * SC * KP2;

    if (i < R1) {
        const float* src = (i < WP) ? wk : wv;
        long j = (i < WP) ? i : i - WP;
        float2 v = ((const float2*)src)[j];
        split_pack(v.x, v.y, wkvH[i], wkvL[i]);
    } else if (i < R2) {
        long j = i - R1;
        if (j < WP) {
            float2 v = ((const float2*)wq)[j];
            split_pack(v.x, v.y, wqH[j], wqL[j]);
        } else {
            long k = j - WP;
            float2 v = ((const float2*)t2w)[k];
            split_pack(v.x, v.y, t2H[k], t2L[k]);
        }
    } else if (i < R3) {
        int t = (int)(i - R2);
        bKV[t] = (t < 512) ? bk[t] : bv[t - 512];
    } else if (i < R4) {
        long j = i - R3;
        int pp  = (int)(j & (KP2 - 1));
        int row = (int)(j / KP2);
        int s   = row & (SC - 1);
        int g   = mask_curr[row];
        int d0  = pp * 2;
        float freq = expf((float)d0 * -0.0179889460176f);
        float ang  = (float)s * freq;
        float v0 = emb[(size_t)g * DM + d0]     + sinf(ang);
        float v1 = emb[(size_t)g * DM + d0 + 1] + cosf(ang);
        split_pack(v0, v1, cH[j], cL[j]);
    }
}

// ---------------- mma / ldmatrix / cp.async helpers ----------------------------
__device__ __forceinline__ void mma_bf16(float* c, const unsigned* a, const unsigned* b) {
    asm("mma.sync.aligned.m16n8k16.row.col.f32.bf16.bf16.f32 "
        "{%0,%1,%2,%3}, {%4,%5,%6,%7}, {%8,%9}, {%0,%1,%2,%3};"
        : "+f"(c[0]), "+f"(c[1]), "+f"(c[2]), "+f"(c[3])
        : "r"(a[0]), "r"(a[1]), "r"(a[2]), "r"(a[3]), "r"(b[0]), "r"(b[1]));
}
__device__ __forceinline__ void cp16(void* dst, const void* src, bool ok) {
    unsigned d = (unsigned)__cvta_generic_to_shared(dst);
    int sz = ok ? 16 : 0;
    asm volatile("cp.async.cg.shared.global [%0], [%1], 16, %2;"
                 :: "r"(d), "l"(src), "r"(sz));
}
#define LDSM4(r, a)                                                          \
    asm volatile("ldmatrix.sync.aligned.m8n8.x4.shared.b16 {%0,%1,%2,%3}, [%4];" \
                 : "=r"((r)[0]), "=r"((r)[1]), "=r"((r)[2]), "=r"((r)[3])    \
                 : "r"(a))

#define PITCH 20
#define TSZ (128*PITCH)
#define F32SZ (128*32)

// ======== fragment-load + mma block shared by all GEMM variants ==============
#define MMA_STEP(baseAH, baseAL, baseBH, baseBL)                                 \
    _Pragma("unroll")                                                            \
    for (int ks = 0; ks < 2; ++ks) {                                             \
        int kc = ks * 8;                                                         \
        unsigned ah[4][4], al[4][4];                                             \
        _Pragma("unroll")                                                        \
        for (int mt = 0; mt < 4; ++mt) {                                         \
            uint32_t off = (uint32_t)(((a_row + mt * 16) * PITCH + kc + a_col) * 4); \
            LDSM4(ah[mt], (baseAH) + off);                                       \
            LDSM4(al[mt], (baseAL) + off);                                       \
        }                                                                        \
        unsigned bh[4][2], bl[4][2];                                             \
        _Pragma("unroll")                                                        \
        for (int np = 0; np < 2; ++np) {                                         \
            uint32_t off = (uint32_t)(((b_row + np * 16) * PITCH + kc + b_col) * 4); \
            unsigned rh[4], rl[4];                                               \
            LDSM4(rh, (baseBH) + off);                                           \
            LDSM4(rl, (baseBL) + off);                                           \
            bh[np * 2][0]     = rh[0]; bh[np * 2][1]     = rh[1];                \
            bh[np * 2 + 1][0] = rh[2]; bh[np * 2 + 1][1] = rh[3];                \
            bl[np * 2][0]     = rl[0]; bl[np * 2][1]     = rl[1];                \
            bl[np * 2 + 1][0] = rl[2]; bl[np * 2 + 1][1] = rl[3];                \
        }                                                                        \
        _Pragma("unroll")                                                        \
        for (int mt = 0; mt < 4; ++mt)                                           \
            _Pragma("unroll")                                                    \
            for (int nt = 0; nt < 4; ++nt)                                       \
                mma_bf16(acc[mt][nt], ah[mt], bh[nt]);                           \
        _Pragma("unroll")                                                        \
        for (int mt = 0; mt < 4; ++mt)                                           \
            _Pragma("unroll")                                                    \
            for (int nt = 0; nt < 4; ++nt)                                       \
                mma_bf16(acc[mt][nt], al[mt], bh[nt]);                           \
        _Pragma("unroll")                                                        \
        for (int mt = 0; mt < 4; ++mt)                                           \
            _Pragma("unroll")                                                    \
            for (int nt = 0; nt < 4; ++nt)                                       \
                mma_bf16(acc[mt][nt], ah[mt], bl[nt]);                           \
    }

#define GEMM_PROLOG()                                                            \
    int bm = blockIdx.x * 128;                                                   \
    int bn = blockIdx.y * 128;                                                   \
    int tid = threadIdx.x;                                                       \
    int wid = tid >> 5;                                                          \
    int lane = tid & 31;                                                         \
    int warp_m = wid >> 2;                                                       \
    int warp_n = wid & 3;                                                        \
    int g  = lane >> 2;                                                          \
    int tg = lane & 3;                                                           \
    int m_base = warp_m * 64;                                                    \
    int n_base = warp_n * 32;                                                    \
    int a_row = m_base + (lane & 15);                                            \
    int a_col = (lane >> 4) * 4;                                                 \
    int b_row = n_base + ((lane >> 4) & 1) * 8 + (lane & 7);                     \
    int b_col = ((lane >> 3) & 1) * 4;                                           \
    float acc[4][4][4];                                                          \
    _Pragma("unroll")                                                            \
    for (int mt = 0; mt < 4; ++mt)                                               \
        _Pragma("unroll")                                                        \
        for (int nt = 0; nt < 4; ++nt)                                           \
            _Pragma("unroll")                                                    \
            for (int i = 0; i < 4; ++i) acc[mt][nt][i] = 0.f;                    \
    int srow0 = tid >> 2;                                                        \
    int sc4   = (tid & 3) * 4;                                                   \
    int srow1 = (tid + 256) >> 2;

#define STAGE_PK(buf, k0p)                                                       \
    {                                                                            \
        unsigned* bAH = sm + (buf) * 4 * TSZ;                                    \
        unsigned* bAL = bAH + TSZ;                                               \
        unsigned* bBH = bAH + 2 * TSZ;                                           \
        unsigned* bBL = bAH + 3 * TSZ;                                           \
        _Pragma("unroll")                                                        \
        for (int i = 0; i < 2; ++i) {                                            \
            int row = i ? srow1 : srow0;                                         \
            cp16(bAH + row * PITCH + sc4, AH + (size_t)(bm + row) * KP2 + (k0p) + sc4, true); \
            cp16(bAL + row * PITCH + sc4, AL + (size_t)(bm + row) * KP2 + (k0p) + sc4, true); \
            int nrow = bn + row;                                                 \
            bool ok = nrow < N;                                                  \
            size_t bro = (size_t)(ok ? nrow : 0) * KP2 + (k0p) + sc4;            \
            cp16(bBH + row * PITCH + sc4, BH + bro, ok);                         \
            cp16(bBL + row * PITCH + sc4, BL + bro, ok);                         \
        }                                                                        \
        asm volatile("cp.async.commit_group;");                                  \
    }

#define GEMM_MAINLOOP()                                                          \
    STAGE_PK(0, 0);                                                              \
    const int NSTEP = DM / 32;                                                   \
    for (int s = 0; s < NSTEP; ++s) {                                            \
        if (s + 1 < NSTEP) {                                                     \
            STAGE_PK((s + 1) & 1, (s + 1) * 16);                                 \
            asm volatile("cp.async.wait_group 1;");                              \
        } else {                                                                 \
            asm volatile("cp.async.wait_group 0;");                              \
        }                                                                        \
        __syncthreads();                                                         \
        uint32_t baseAH = smem_u32 + ((s & 1) * 4 * TSZ) * 4;                    \
        MMA_STEP(baseAH, baseAH + TSZ * 4, baseAH + 2 * TSZ * 4, baseAH + 3 * TSZ * 4); \
        __syncthreads();                                                         \
    }

// ---------------- GEMM variant 1: packed A/B, f32 C + bias --------------------
__global__ __launch_bounds__(256, 2)
void gemm_pk_kernel(const unsigned* __restrict__ AH, const unsigned* __restrict__ AL,
                    const unsigned* __restrict__ BH, const unsigned* __restrict__ BL,
                    const float* __restrict__ bias,
                    float* __restrict__ C,
                    int M, int N, int ldc) {
    extern __shared__ unsigned sm[];
    uint32_t smem_u32 = (uint32_t)__cvta_generic_to_shared(sm);
    GEMM_PROLOG();
    GEMM_MAINLOOP();

#pragma unroll
    for (int mt = 0; mt < 4; ++mt) {
        int row0 = bm + m_base + mt * 16 + g;
#pragma unroll
        for (int nt = 0; nt < 4; ++nt) {
            int col0 = bn + n_base + nt * 8 + 2 * tg;
            float b0 = bias ? bias[col0] : 0.f;
            float b1 = bias ? bias[col0 + 1] : 0.f;
            C[(size_t)row0 * ldc + col0]           = acc[mt][nt][0] + b0;
            C[(size_t)row0 * ldc + col0 + 1]       = acc[mt][nt][1] + b1;
            C[(size_t)(row0 + 8) * ldc + col0]     = acc[mt][nt][2] + b0;
            C[(size_t)(row0 + 8) * ldc + col0 + 1] = acc[mt][nt][3] + b1;
        }
    }
}

// ---------------- GEMM variant 1b: Q projection with fused mask gather --------
__global__ __launch_bounds__(256, 2)
void gemm_pk_qproj_kernel(const int* __restrict__ mask_pos,
                          const unsigned* __restrict__ AH, const unsigned* __restrict__ AL,
                          const unsigned* __restrict__ BH, const unsigned* __restrict__ BL,
                          const float* __restrict__ bias,
                          float* __restrict__ C) {
    extern __shared__ unsigned sm[];
    uint32_t smem_u32 = (uint32_t)__cvta_generic_to_shared(sm);
    const int ldc = DM;
    GEMM_PROLOG();

    int gr0 = bm + srow0;
    int gr1 = bm + srow1;
    size_t abase0 = (((size_t)(gr0 >> 4)) * SC + mask_pos[gr0]) * KP2 + sc4;
    size_t abase1 = (((size_t)(gr1 >> 4)) * SC + mask_pos[gr1]) * KP2 + sc4;

#define STAGE_QP(buf, k0p)                                                       \
    {                                                                            \
        unsigned* bAH = sm + (buf) * 4 * TSZ;                                    \
        unsigned* bAL = bAH + TSZ;                                               \
        unsigned* bBH = bAH + 2 * TSZ;                                           \
        unsigned* bBL = bAH + 3 * TSZ;                                           \
        cp16(bAH + srow0 * PITCH + sc4, AH + abase0 + (k0p), true);              \
        cp16(bAL + srow0 * PITCH + sc4, AL + abase0 + (k0p), true);              \
        cp16(bAH + srow1 * PITCH + sc4, AH + abase1 + (k0p), true);              \
        cp16(bAL + srow1 * PITCH + sc4, AL + abase1 + (k0p), true);              \
        cp16(bBH + srow0 * PITCH + sc4, BH + (size_t)(bn + srow0) * KP2 + (k0p) + sc4, true); \
        cp16(bBL + srow0 * PITCH + sc4, BL + (size_t)(bn + srow0) * KP2 + (k0p) + sc4, true); \
        cp16(bBH + srow1 * PITCH + sc4, BH + (size_t)(bn + srow1) * KP2 + (k0p) + sc4, true); \
        cp16(bBL + srow1 * PITCH + sc4, BL + (size_t)(bn + srow1) * KP2 + (k0p) + sc4, true); \
        asm volatile("cp.async.commit_group;");                                  \
    }

    STAGE_QP(0, 0);
    const int NSTEP = DM / 32;
    for (int s = 0; s < NSTEP; ++s) {
        if (s + 1 < NSTEP) {
            STAGE_QP((s + 1) & 1, (s + 1) * 16);
            asm volatile("cp.async.wait_group 1;");
        } else {
            asm volatile("cp.async.wait_group 0;");
        }
        __syncthreads();
        uint32_t baseAH = smem_u32 + ((s & 1) * 4 * TSZ) * 4;
        MMA_STEP(baseAH, baseAH + TSZ * 4, baseAH + 2 * TSZ * 4, baseAH + 3 * TSZ * 4);
        __syncthreads();
    }
#undef STAGE_QP

#pragma unroll
    for (int mt = 0; mt < 4; ++mt) {
        int row0 = bm + m_base + mt * 16 + g;
#pragma unroll
        for (int nt = 0; nt < 4; ++nt) {
            int col0 = bn + n_base + nt * 8 + 2 * tg;
            float b0 = bias[col0], b1 = bias[col0 + 1];
            C[(size_t)row0 * ldc + col0]           = acc[mt][nt][0] + b0;
            C[(size_t)row0 * ldc + col0 + 1]       = acc[mt][nt][1] + b1;
            C[(size_t)(row0 + 8) * ldc + col0]     = acc[mt][nt][2] + b0;
            C[(size_t)(row0 + 8) * ldc + col0 + 1] = acc[mt][nt][3] + b1;
        }
    }
}

// ---------------- GEMM variant 2: t2 with fused tanh(A) conversion + packout ---
__global__ __launch_bounds__(256, 2)
void gemm_t2_kernel(const float* __restrict__ Af,
                    const unsigned* __restrict__ BH, const unsigned* __restrict__ BL,
                    const float* __restrict__ bias,
                    unsigned* __restrict__ CH, unsigned* __restrict__ CL) {
    extern __shared__ unsigned sm[];
    uint32_t smem_u32 = (uint32_t)__cvta_generic_to_shared(sm);
    GEMM_PROLOG();
    int frow = tid >> 3;
    int fq   = (tid & 7) * 4;

#define STAGE_T2(buf, s)                                                         \
    {                                                                            \
        unsigned* bAH = sm + (buf) * 4 * TSZ;                                    \
        unsigned* bBH = bAH + 2 * TSZ;                                           \
        unsigned* bBL = bAH + 3 * TSZ;                                           \
        float* aF = (float*)(sm + 8 * TSZ + (buf) * F32SZ);                      \
        int k0p = (s) * 16;                                                      \
        _Pragma("unroll")                                                        \
        for (int j = 0; j < 4; ++j) {                                            \
            int row = frow + j * 32;                                             \
            cp16(aF + row * 32 + fq, Af + (size_t)(bm + row) * DM + (s) * 32 + fq, true); \
        }                                                                        \
        cp16(bBH + srow0 * PITCH + sc4, BH + (size_t)(bn + srow0) * KP2 + k0p + sc4, true); \
        cp16(bBL + srow0 * PITCH + sc4, BL + (size_t)(bn + srow0) * KP2 + k0p + sc4, true); \
        cp16(bBH + srow1 * PITCH + sc4, BH + (size_t)(bn + srow1) * KP2 + k0p + sc4, true); \
        cp16(bBL + srow1 * PITCH + sc4, BL + (size_t)(bn + srow1) * KP2 + k0p + sc4, true); \
        asm volatile("cp.async.commit_group;");                                  \
    }

    STAGE_T2(0, 0);
    const int NSTEP = DM / 32;
    for (int s = 0; s < NSTEP; ++s) {
        if (s + 1 < NSTEP) {
            STAGE_T2((s + 1) & 1, s + 1);
            asm volatile("cp.async.wait_group 1;");
        } else {
            asm volatile("cp.async.wait_group 0;");
        }
        __syncthreads();

        {
            unsigned* bAH = sm + (s & 1) * 4 * TSZ;
            unsigned* bAL = bAH + TSZ;
            const float* aF = (const float*)(sm + 8 * TSZ + (s & 1) * F32SZ);
#pragma unroll
            for (int j = 0; j < 8; ++j) {
                int idx = tid + j * 256;
                int row = idx >> 4;
                int p   = idx & 15;
                float x = tanhf(aF[row * 32 + 2 * p]);
                float y = tanhf(aF[row * 32 + 2 * p + 1]);
                split_pack(x, y, bAH[row * PITCH + p], bAL[row * PITCH + p]);
            }
        }
        __syncthreads();

        uint32_t baseAH = smem_u32 + ((s & 1) * 4 * TSZ) * 4;
        MMA_STEP(baseAH, baseAH + TSZ * 4, baseAH + 2 * TSZ * 4, baseAH + 3 * TSZ * 4);
        __syncthreads();
    }
#undef STAGE_T2

#pragma unroll
    for (int mt = 0; mt < 4; ++mt) {
        int row0 = bm + m_base + mt * 16 + g;
#pragma unroll
        for (int nt = 0; nt < 4; ++nt) {
            int col0 = bn + n_base + nt * 8 + 2 * tg;
            float b0 = bias[col0], b1 = bias[col0 + 1];
            float v0 = acc[mt][nt][0] + b0, v1 = acc[mt][nt][1] + b1;
            float v2 = acc[mt][nt][2] + b0, v3 = acc[mt][nt][3] + b1;
            size_t p0 = (size_t)row0 * KP2 + (col0 >> 1);
            size_t p1 = (size_t)(row0 + 8) * KP2 + (col0 >> 1);
            split_pack(v0, v1, CH[p0], CL[p0]);
            split_pack(v2, v3, CH[p1], CL[p1]);
        }
    }
}

// ---------------- GEMM variant 3: scores, f32 B (emb) converted in-kernel ------
__global__ __launch_bounds__(256, 2)
void gemm_score_kernel(const unsigned* __restrict__ AH, const unsigned* __restrict__ AL,
                       const float* __restrict__ Bf,
                       float* __restrict__ C,
                       float2* __restrict__ part,
                       int N) {
    extern __shared__ unsigned sm[];
    uint32_t smem_u32 = (uint32_t)__cvta_generic_to_shared(sm);
    GEMM_PROLOG();
    int brow = tid >> 3;
    int bq   = (tid & 7) * 4;

#define STAGE_SC(buf, s)                                                         \
    {                                                                            \
        unsigned* bAH = sm + (buf) * 4 * TSZ;                                    \
        unsigned* bAL = bAH + TSZ;                                               \
        float* bF = (float*)(sm + 8 * TSZ + (buf) * F32SZ);                      \
        int k0p = (s) * 16;                                                      \
        cp16(bAH + srow0 * PITCH + sc4, AH + (size_t)(bm + srow0) * KP2 + k0p + sc4, true); \
        cp16(bAL + srow0 * PITCH + sc4, AL + (size_t)(bm + srow0) * KP2 + k0p + sc4, true); \
        cp16(bAH + srow1 * PITCH + sc4, AH + (size_t)(bm + srow1) * KP2 + k0p + sc4, true); \
        cp16(bAL + srow1 * PITCH + sc4, AL + (size_t)(bm + srow1) * KP2 + k0p + sc4, true); \
        _Pragma("unroll")                                                        \
        for (int j = 0; j < 4; ++j) {                                            \
            int row = brow + j * 32;                                             \
            int nrow = bn + row;                                                 \
            bool ok = nrow < N;                                                  \
            cp16(bF + row * 32 + bq,                                             \
                 Bf + (size_t)(ok ? nrow : 0) * DM + (s) * 32 + bq, ok);         \
        }                                                                        \
        asm volatile("cp.async.commit_group;");                                  \
    }

    STAGE_SC(0, 0);
    const int NSTEP = DM / 32;
    for (int s = 0; s < NSTEP; ++s) {
        if (s + 1 < NSTEP) {
            STAGE_SC((s + 1) & 1, s + 1);
            asm volatile("cp.async.wait_group 1;");
        } else {
            asm volatile("cp.async.wait_group 0;");
        }
        __syncthreads();

        {
            unsigned* bAH0 = sm + (s & 1) * 4 * TSZ;
            unsigned* bBH = bAH0 + 2 * TSZ;
            unsigned* bBL = bAH0 + 3 * TSZ;
            const float* bF = (const float*)(sm + 8 * TSZ + (s & 1) * F32SZ);
#pragma unroll
            for (int j = 0; j < 8; ++j) {
                int idx = tid + j * 256;
                int row = idx >> 4;
                int p   = idx & 15;
                float x = bF[row * 32 + 2 * p];
                float y = bF[row * 32 + 2 * p + 1];
                unsigned hi;
                asm("cvt.rn.bf16x2.f32 %0, %1, %2;" : "=r"(hi) : "f"(y), "f"(x));
                float hx = __uint_as_float(hi << 16);
                float hy = __uint_as_float(hi & 0xFFFF0000u);
                unsigned lo;
                asm("cvt.rn.bf16x2.f32 %0, %1, %2;" : "=r"(lo) : "f"(y - hy), "f"(x - hx));
                bBH[row * PITCH + p] = hi;
                bBL[row * PITCH + p] = lo;
            }
        }
        __syncthreads();

        uint32_t baseAH = smem_u32 + ((s & 1) * 4 * TSZ) * 4;
        MMA_STEP(baseAH, baseAH + TSZ * 4, baseAH + 2 * TSZ * 4, baseAH + 3 * TSZ * 4);
        __syncthreads();
    }
#undef STAGE_SC

    float2* red = (float2*)sm;
#pragma unroll
    for (int mt = 0; mt < 4; ++mt) {
        int rl0 = m_base + mt * 16 + g;
        int row0 = bm + rl0;
        float m0 = -INFINITY, s0 = 0.f, m1 = -INFINITY, s1 = 0.f;
#pragma unroll
        for (int nt = 0; nt < 4; ++nt) {
            int col0 = bn + n_base + nt * 8 + 2 * tg;
            float v00 = acc[mt][nt][0], v01 = acc[mt][nt][1];
            float v10 = acc[mt][nt][2], v11 = acc[mt][nt][3];
            if (col0 < N) {
                C[(size_t)row0 * N + col0]       = v00;
                C[(size_t)(row0 + 8) * N + col0] = v10;
                float nm0 = fmaxf(m0, v00); s0 = s0 * __expf(m0 - nm0) + __expf(v00 - nm0); m0 = nm0;
                float nm1 = fmaxf(m1, v10); s1 = s1 * __expf(m1 - nm1) + __expf(v10 - nm1); m1 = nm1;
            }
            if (col0 + 1 < N) {
                C[(size_t)row0 * N + col0 + 1]       = v01;
                C[(size_t)(row0 + 8) * N + col0 + 1] = v11;
                float nm0 = fmaxf(m0, v01); s0 = s0 * __expf(m0 - nm0) + __expf(v01 - nm0); m0 = nm0;
                float nm1 = fmaxf(m1, v11); s1 = s1 * __expf(m1 - nm1) + __expf(v11 - nm1); m1 = nm1;
            }
        }
        int slot = warp_n * 4 + tg;
        red[rl0 * 16 + slot]       = make_float2(m0, s0);
        red[(rl0 + 8) * 16 + slot] = make_float2(m1, s1);
    }
    __syncthreads();
    if (tid < 128) {
        float m = -INFINITY, s = 0.f;
#pragma unroll
        for (int k = 0; k < 16; ++k) {
            float2 v = red[tid * 16 + k];
            float nm = fmaxf(m, v.x);
            s = s * __expf(m - nm) + v.y * __expf(v.x - nm);
            m = nm;
        }
        part[(size_t)blockIdx.y * MQ + bm + tid] = make_float2(m, s);
    }
}

// ---------------- attention (reg-capped for 4 CTAs/SM) ------------------------
__global__ __launch_bounds__(256, 4)
void attn_kernel(const float* __restrict__ Q,
                 const float* __restrict__ KV,
                 float* __restrict__ out) {
    int blk = blockIdx.x;
    int b = blk / HH, h = blk % HH;

    __shared__ float sQ[NM][DH];
    __shared__ float sS[NM][SC];
    __shared__ float sKV[SC][DH + 1];

    int tid = threadIdx.x;

    for (int e = tid; e < NM * DH; e += 256) {
        int m = e / DH, d0 = e % DH;
        sQ[m][d0] = Q[((size_t)b * NM + m) * DM + h * DH + d0];
    }
    for (int e = tid; e < SC * DH; e += 256) {
        int k = e / DH, d0 = e % DH;
        sKV[k][d0] = KV[((size_t)b * SC + k) * 1024 + h * DH + d0];
    }
    __syncthreads();

    for (int e = tid; e < NM * SC; e += 256) {
        int m = e / SC, k = e % SC;
        float acc = 0.f;
#pragma unroll 16
        for (int d0 = 0; d0 < DH; ++d0) acc += sQ[m][d0] * sKV[k][d0];
        sS[m][k] = acc;
    }
    __syncthreads();

    int w = tid >> 5, lane = tid & 31;
    for (int m = 2 * w; m < 2 * w + 2; ++m) {
        float vals[4];
        float mx = -INFINITY;
#pragma unroll
        for (int j = 0; j < 4; ++j) {
            vals[j] = sS[m][lane * 4 + j];
            mx = fmaxf(mx, vals[j]);
        }
#pragma unroll
        for (int off = 16; off; off >>= 1)
            mx = fmaxf(mx, __shfl_xor_sync(0xffffffffu, mx, off));
        float sum = 0.f;
#pragma unroll
        for (int j = 0; j < 4; ++j) {
            vals[j] = expf(vals[j] - mx);
            sum += vals[j];
        }
#pragma unroll
        for (int off = 16; off; off >>= 1)
            sum += __shfl_xor_sync(0xffffffffu, sum, off);
        float inv = 1.f / sum;
#pragma unroll
        for (int j = 0; j < 4; ++j) sS[m][lane * 4 + j] = vals[j] * inv;
    }
    __syncthreads();

    for (int e = tid; e < SC * DH; e += 256) {
        int k = e / DH, d0 = e % DH;
        sKV[k][d0] = KV[((size_t)b * SC + k) * 1024 + 512 + h * DH + d0];
    }
    __syncthreads();

    for (int e = tid; e < NM * DH; e += 256) {
        int m = e / DH, d0 = e % DH;
        float acc = 0.f;
#pragma unroll 8
        for (int k = 0; k < SC; ++k) acc += sS[m][k] * sKV[k][d0];
        out[((size_t)b * NM + m) * DM + h * DH + d0] = acc;
    }
}

// ---------------- fused LSE reduce + subtract (block per row) -----------------
__global__ __launch_bounds__(256)
void lse_sub_kernel(const float2* __restrict__ part, float* __restrict__ out) {
    int row = blockIdx.x;
    __shared__ float rm[256], rs[256];
    int t = threadIdx.x;

    float m = -INFINITY, s = 0.f;
    for (int c = t; c < NCHUNK; c += 256) {
        float2 v = part[(size_t)c * MQ + row];
        float nm = fmaxf(m, v.x);
        s = s * __expf(m - nm) + v.y * __expf(v.x - nm);
        m = nm;
    }
    rm[t] = m; rs[t] = s;
    __syncthreads();
    for (int st = 128; st; st >>= 1) {
        if (t < st) {
            float m2 = rm[t + st], s2 = rs[t + st];
            float nm = fmaxf(rm[t], m2);
            rs[t] = rs[t] * __expf(rm[t] - nm) + s2 * __expf(m2 - nm);
            rm[t] = nm;
        }
        __syncthreads();
    }
    float lse = rm[0] + logf(rs[0]);

    float* p = out + (size_t)row * NC;
    for (int i = t; i < NC; i += 256) p[i] -= lse;
}

// ---------------- launch -----------------------------------------------------
extern "C" void kernel_launch(void* const* d_in, const int* in_sizes, int n_in,
                              void* d_out, int out_size) {
    const int*   mask_pos  = (const int*)d_in[2];
    const int*   mask_curr = (const int*)d_in[3];
    const float* emb       = (const float*)d_in[5];
    const float* c_wq = (const float*)d_in[12];
    const float* c_bq = (const float*)d_in[13];
    const float* c_wk = (const float*)d_in[14];
    const float* c_bk = (const float*)d_in[15];
    const float* c_wv = (const float*)d_in[16];
    const float* c_bv = (const float*)d_in[17];
    const float* t2_w = (const float*)d_in[24];
    const float* t2_b = (const float*)d_in[25];
    float* out = (float*)d_out;

    float *KV, *Qb, *attn, *bKV;
    float2* part;
    cudaGetSymbolAddress((void**)&KV,   g_KV);
    cudaGetSymbolAddress((void**)&Qb,   g_Q);
    cudaGetSymbolAddress((void**)&attn, g_attn);
    cudaGetSymbolAddress((void**)&bKV,  g_bKV);
    cudaGetSymbolAddress((void**)&part, g_part);

    unsigned *currH, *currL, *wkvH, *wkvL, *wqH, *wqL, *t2H, *t2L, *hybH, *hybL;
    cudaGetSymbolAddress((void**)&currH, g_pk_currH);
    cudaGetSymbolAddress((void**)&currL, g_pk_currL);
    cudaGetSymbolAddress((void**)&wkvH,  g_pk_wkvH);
    cudaGetSymbolAddress((void**)&wkvL,  g_pk_wkvL);
    cudaGetSymbolAddress((void**)&wqH,   g_pk_wqH);
    cudaGetSymbolAddress((void**)&wqL,   g_pk_wqL);
    cudaGetSymbolAddress((void**)&t2H,   g_pk_t2H);
    cudaGetSymbolAddress((void**)&t2L,   g_pk_t2L);
    cudaGetSymbolAddress((void**)&hybH,  g_pk_hybH);
    cudaGetSymbolAddress((void**)&hybL,  g_pk_hybL);

    const int SMEMB  = 2 * 4 * TSZ * 4;                // 81920 B
    const int SMEMSC = (8 * TSZ + 2 * F32SZ) * 4;      // 114688 B
    cudaFuncSetAttribute(gemm_pk_kernel,
                         cudaFuncAttributeMaxDynamicSharedMemorySize, SMEMB);
    cudaFuncSetAttribute(gemm_pk_qproj_kernel,
                         cudaFuncAttributeMaxDynamicSharedMemorySize, SMEMB);
    cudaFuncSetAttribute(gemm_t2_kernel,
                         cudaFuncAttributeMaxDynamicSharedMemorySize, SMEMSC);
    cudaFuncSetAttribute(gemm_score_kernel,
                         cudaFuncAttributeMaxDynamicSharedMemorySize, SMEMSC);

    // 0: merged prologue (all weight prepacks + bias + gather_pe)
    {
        long total = 4 * WP + 1024 + (long)BB * SC * KP2;
        prologue_kernel<<<(int)((total + 255) / 256), 256>>>(
            mask_curr, emb, c_wk, c_wv, c_wq, t2_w, c_bk, c_bv,
            wkvH, wkvL, wqH, wqL, t2H, t2L, bKV, currH, currL);
    }
    // 1: Q projection with fused mask gather
    {
        dim3 g(MQ / 128, DM / 128);
        gemm_pk_qproj_kernel<<<g, 256, SMEMB>>>(mask_pos, currH, currL, wqH, wqL, c_bq, Qb);
    }
    // 2: merged K|V projection [4096, 1024]
    {
        dim3 g((BB * SC) / 128, 1024 / 128);
        gemm_pk_kernel<<<g, 256, SMEMB>>>(currH, currL, wkvH, wkvL, bKV, KV,
                                          BB * SC, 1024, 1024);
    }
    // 3: attention
    attn_kernel<<<BB * HH, 256>>>(Qb, KV, attn);
    // 4: t2 GEMM with fused tanh(A) conversion, packed output
    {
        dim3 g(MQ / 128, DM / 128);
        gemm_t2_kernel<<<g, 256, SMEMSC>>>(attn, t2H, t2L, t2_b, hybH, hybL);
    }
    // 5: scores GEMM
    {
        dim3 g(MQ / 128, NCHUNK);
        gemm_score_kernel<<<g, 256, SMEMSC>>>(hybH, hybL, emb + 2 * DM, out, part, NC);
    }
    // 6: fused lse reduce + subtract
    lse_sub_kernel<<<MQ, 256>>>(part, out);
}